// round 13
// baseline (speedup 1.0000x reference)
#include <cuda_runtime.h>
#include <cuda_bf16.h>
#include <cstdint>

#define OUT_DIM 64
#define IN_DIM 128
#define MAX_POOL 16384
#define MAX_EDGES 65536
#define CAP 32                 // bucket capacity per pool entry

__device__ int g_counts[MAX_POOL + 1];        // bucket alloc cursors + spill counter
__device__ int g_bucket[MAX_POOL * CAP];      // memset to -1 each call
__device__ int g_spill[MAX_EDGES];

// ---------------------------------------------------------------------------
// Single-pass counting scatter into fixed-capacity buckets; overflow -> spill.
__global__ void bucket_kernel(const int* __restrict__ idx, int E, int npool) {
    int i = blockIdx.x * blockDim.x + threadIdx.x;
    if (i < E) {
        int id = idx[i];
        int p = atomicAdd(&g_counts[id], 1);
        if (p < CAP) {
            g_bucket[id * CAP + p] = i;
        } else {
            int s = atomicAdd(&g_counts[npool], 1);
            if (s < MAX_EDGES) g_spill[s] = i;
        }
    }
}

// ---------------------------------------------------------------------------
__device__ __forceinline__ void partials8(float v[8], const float4 wv[8],
                                          const float4& xv) {
    #pragma unroll
    for (int i = 0; i < 8; i++) v[i] = wv[i].x * xv.x;
    #pragma unroll
    for (int i = 0; i < 8; i++) v[i] = fmaf(wv[i].y, xv.y, v[i]);
    #pragma unroll
    for (int i = 0; i < 8; i++) v[i] = fmaf(wv[i].z, xv.z, v[i]);
    #pragma unroll
    for (int i = 0; i < 8; i++) v[i] = fmaf(wv[i].w, xv.w, v[i]);
}

// 5-stage butterfly: 8 row-partials x 32 lanes -> final row value in lanes 0..7
__device__ __forceinline__ float fold8(const float v[8], int lane) {
    bool b0 = lane & 1;
    float a0, a1, a2, a3;
    {
        float p0 = __shfl_xor_sync(~0u, v[0], 1), p1 = __shfl_xor_sync(~0u, v[1], 1);
        float p2 = __shfl_xor_sync(~0u, v[2], 1), p3 = __shfl_xor_sync(~0u, v[3], 1);
        float p4 = __shfl_xor_sync(~0u, v[4], 1), p5 = __shfl_xor_sync(~0u, v[5], 1);
        float p6 = __shfl_xor_sync(~0u, v[6], 1), p7 = __shfl_xor_sync(~0u, v[7], 1);
        a0 = b0 ? (v[4] + p4) : (v[0] + p0);
        a1 = b0 ? (v[5] + p5) : (v[1] + p1);
        a2 = b0 ? (v[6] + p6) : (v[2] + p2);
        a3 = b0 ? (v[7] + p7) : (v[3] + p3);
    }
    bool b1 = lane & 2;
    float c0, c1;
    {
        float q0 = __shfl_xor_sync(~0u, a0, 2), q1 = __shfl_xor_sync(~0u, a1, 2);
        float q2 = __shfl_xor_sync(~0u, a2, 2), q3 = __shfl_xor_sync(~0u, a3, 2);
        c0 = b1 ? (a2 + q2) : (a0 + q0);
        c1 = b1 ? (a3 + q3) : (a1 + q1);
    }
    bool b2 = lane & 4;
    float s0 = __shfl_xor_sync(~0u, c0, 4), s1 = __shfl_xor_sync(~0u, c1, 4);
    float acc = b2 ? (c1 + s1) : (c0 + s0);
    acc += __shfl_xor_sync(~0u, acc, 8);
    acc += __shfl_xor_sync(~0u, acc, 16);
    return acc;
}

// ---------------------------------------------------------------------------
// Persistent compute, register-double-buffered W: next group's 8 LDG.128 are
// issued BEFORE computing the current group, so the fetch latency hides under
// the whole compute phase. No SMEM, no barriers, warp-autonomous.
__global__ __launch_bounds__(256, 2) void compute_kernel(
    const float* __restrict__ x,      // [E, 128]
    const float* __restrict__ Wpool,  // [P, 64, 128]
    const float* __restrict__ bpool,  // [P, 64]
    float* __restrict__ out,          // [E, 64]
    int npool)
{
    int warp = threadIdx.x >> 5;
    int lane = threadIdx.x & 31;
    int stride = gridDim.x;

    int rloc = 4 * (lane & 1) + 2 * ((lane >> 1) & 1) + ((lane >> 2) & 1);
    int orow = 8 * warp + rloc;

    const float4* X  = reinterpret_cast<const float4*>(x);
    const float4* WP = reinterpret_cast<const float4*>(Wpool);
    float4 z = make_float4(0.f, 0.f, 0.f, 0.f);

    int w = blockIdx.x;

    // prologue: first group's edge ids + W
    int se = -1;
    float4 wv[8];
    if (w < npool) {
        se = g_bucket[w * CAP + lane];
        const float4* Wg = WP + (size_t)w * 2048 + warp * 256;
        #pragma unroll
        for (int i = 0; i < 8; i++)
            wv[i] = Wg[i * 32 + lane];   // wv[i] = W[8*warp+i][4l..4l+4)
    }

    while (w < npool) {
        // Issue NEXT group's loads first: they land during this group's compute.
        int wn = w + stride;
        int se_next = -1;
        float4 wn_v[8];
        if (wn < npool) {
            se_next = g_bucket[wn * CAP + lane];
            const float4* Wg = WP + (size_t)wn * 2048 + warp * 256;
            #pragma unroll
            for (int i = 0; i < 8; i++)
                wn_v[i] = Wg[i * 32 + lane];
        }

        int c = __popc(__ballot_sync(~0u, se >= 0));     // group size 0..32
        if (c > 0) {
            float bias = bpool[(size_t)w * OUT_DIM + orow];

            // prime pair pipeline: edges 0,1
            int eA = __shfl_sync(~0u, se, 0);
            int eB = __shfl_sync(~0u, se, 1);
            float4 xA = X[(size_t)eA * 32 + lane];
            float4 xB = (c > 1) ? X[(size_t)eB * 32 + lane] : z;

            int t = 0;
            while (t + 2 <= c) {
                int eC = __shfl_sync(~0u, se, (t + 2) & 31);
                int eD = __shfl_sync(~0u, se, (t + 3) & 31);
                float4 xC = z, xD = z;
                if (t + 2 < c) xC = X[(size_t)eC * 32 + lane];
                if (t + 3 < c) xD = X[(size_t)eD * 32 + lane];

                float vA[8], vB[8];
                partials8(vA, wv, xA);
                partials8(vB, wv, xB);
                float accA = fold8(vA, lane);
                float accB = fold8(vB, lane);

                if (lane < 8) {
                    float yA = accA + bias;
                    float yB = accB + bias;
                    out[(size_t)eA * OUT_DIM + orow] = yA > 0.f ? yA : 0.f;
                    out[(size_t)eB * OUT_DIM + orow] = yB > 0.f ? yB : 0.f;
                }

                eA = eC; xA = xC;
                eB = eD; xB = xD;
                t += 2;
            }
            if (t < c) {                         // odd tail
                float vA[8];
                partials8(vA, wv, xA);
                float accA = fold8(vA, lane);
                if (lane < 8) {
                    float yA = accA + bias;
                    out[(size_t)eA * OUT_DIM + orow] = yA > 0.f ? yA : 0.f;
                }
            }
        }

        // rotate buffers
        w = wn;
        se = se_next;
        #pragma unroll
        for (int i = 0; i < 8; i++) wv[i] = wn_v[i];
    }
}

// ---------------------------------------------------------------------------
// Spill slow path: normally zero work, early exit.
__global__ __launch_bounds__(256) void spill_kernel(
    const float* __restrict__ x,
    const float* __restrict__ Wpool,
    const float* __restrict__ bpool,
    const int*   __restrict__ idx,
    float* __restrict__ out,
    int npool)
{
    int nspill = g_counts[npool];
    if (nspill == 0) return;
    if (nspill > MAX_EDGES) nspill = MAX_EDGES;

    int warp = threadIdx.x >> 5;
    int lane = threadIdx.x & 31;
    const float4* X = reinterpret_cast<const float4*>(x);

    for (int s = blockIdx.x * 8 + warp; s < nspill; s += gridDim.x * 8) {
        int e = g_spill[s];
        int p = idx[e];
        const float4* Wr = reinterpret_cast<const float4*>(Wpool) + (size_t)p * 2048;
        #pragma unroll
        for (int rr = 0; rr < 2; rr++) {
            int row = lane * 2 + rr;
            float acc = 0.f;
            for (int kk = 0; kk < 32; kk++) {
                float4 a = Wr[row * 32 + kk];
                float4 b = X[(size_t)e * 32 + kk];
                acc = fmaf(a.x, b.x, acc);
                acc = fmaf(a.y, b.y, acc);
                acc = fmaf(a.z, b.z, acc);
                acc = fmaf(a.w, b.w, acc);
            }
            acc += bpool[(size_t)p * OUT_DIM + row];
            out[(size_t)e * OUT_DIM + row] = acc > 0.f ? acc : 0.f;
        }
    }
}

// ---------------------------------------------------------------------------
extern "C" void kernel_launch(void* const* d_in, const int* in_sizes, int n_in,
                              void* d_out, int out_size) {
    const float* x     = (const float*)d_in[0];  // [E,128,1]
    const int*   idx   = (const int*)d_in[1];    // [E]
    const float* Wpool = (const float*)d_in[2];  // [P,64,128]
    const float* bpool = (const float*)d_in[3];  // [P,64,1]
    float* out = (float*)d_out;                  // [E,64,1]

    int E     = in_sizes[1];
    int npool = in_sizes[3] / OUT_DIM;
    if (npool > MAX_POOL) npool = MAX_POOL;      // defensive

    void* counts_ptr = nullptr;
    void* bucket_ptr = nullptr;
    cudaGetSymbolAddress(&counts_ptr, g_counts);
    cudaGetSymbolAddress(&bucket_ptr, g_bucket);
    cudaMemsetAsync(counts_ptr, 0, (size_t)(npool + 1) * sizeof(int));
    cudaMemsetAsync(bucket_ptr, 0xFF, (size_t)npool * CAP * sizeof(int));

    int sms = 148;
    cudaDeviceGetAttribute(&sms, cudaDevAttrMultiProcessorCount, 0);

    int eb = (E + 255) / 256;
    bucket_kernel<<<eb, 256>>>(idx, E, npool);

    int cgrid = 2 * sms;
    if (cgrid > npool) cgrid = npool;
    compute_kernel<<<cgrid, 256>>>(x, Wpool, bpool, out, npool);
    spill_kernel<<<64, 256>>>(x, Wpool, bpool, idx, out, npool);
}

// round 14
// speedup vs baseline: 1.2145x; 1.2145x over previous
#include <cuda_runtime.h>
#include <cuda_bf16.h>
#include <cstdint>

#define OUT_DIM 64
#define IN_DIM 128
#define MAX_POOL 16384
#define MAX_EDGES 65536
#define CAP 32                 // bucket capacity per pool entry

__device__ int g_counts[MAX_POOL + 1];        // bucket alloc cursors + spill counter
__device__ int g_bucket[MAX_POOL * CAP];      // memset to -1 each call
__device__ int g_spill[MAX_EDGES];

// ---------------------------------------------------------------------------
// Single-pass counting scatter into fixed-capacity buckets; overflow -> spill.
__global__ void bucket_kernel(const int* __restrict__ idx, int E, int npool) {
    int i = blockIdx.x * blockDim.x + threadIdx.x;
    if (i < E) {
        int id = idx[i];
        int p = atomicAdd(&g_counts[id], 1);
        if (p < CAP) {
            g_bucket[id * CAP + p] = i;
        } else {
            int s = atomicAdd(&g_counts[npool], 1);
            if (s < MAX_EDGES) g_spill[s] = i;
        }
    }
}

// ---------------------------------------------------------------------------
__device__ __forceinline__ void partials8(float v[8], const float4 wv[8],
                                          const float4& xv) {
    #pragma unroll
    for (int i = 0; i < 8; i++) v[i] = wv[i].x * xv.x;
    #pragma unroll
    for (int i = 0; i < 8; i++) v[i] = fmaf(wv[i].y, xv.y, v[i]);
    #pragma unroll
    for (int i = 0; i < 8; i++) v[i] = fmaf(wv[i].z, xv.z, v[i]);
    #pragma unroll
    for (int i = 0; i < 8; i++) v[i] = fmaf(wv[i].w, xv.w, v[i]);
}

// 5-stage butterfly: 8 row-partials x 32 lanes -> final row value in lanes 0..7
__device__ __forceinline__ float fold8(const float v[8], int lane) {
    bool b0 = lane & 1;
    float a0, a1, a2, a3;
    {
        float p0 = __shfl_xor_sync(~0u, v[0], 1), p1 = __shfl_xor_sync(~0u, v[1], 1);
        float p2 = __shfl_xor_sync(~0u, v[2], 1), p3 = __shfl_xor_sync(~0u, v[3], 1);
        float p4 = __shfl_xor_sync(~0u, v[4], 1), p5 = __shfl_xor_sync(~0u, v[5], 1);
        float p6 = __shfl_xor_sync(~0u, v[6], 1), p7 = __shfl_xor_sync(~0u, v[7], 1);
        a0 = b0 ? (v[4] + p4) : (v[0] + p0);
        a1 = b0 ? (v[5] + p5) : (v[1] + p1);
        a2 = b0 ? (v[6] + p6) : (v[2] + p2);
        a3 = b0 ? (v[7] + p7) : (v[3] + p3);
    }
    bool b1 = lane & 2;
    float c0, c1;
    {
        float q0 = __shfl_xor_sync(~0u, a0, 2), q1 = __shfl_xor_sync(~0u, a1, 2);
        float q2 = __shfl_xor_sync(~0u, a2, 2), q3 = __shfl_xor_sync(~0u, a3, 2);
        c0 = b1 ? (a2 + q2) : (a0 + q0);
        c1 = b1 ? (a3 + q3) : (a1 + q1);
    }
    bool b2 = lane & 4;
    float s0 = __shfl_xor_sync(~0u, c0, 4), s1 = __shfl_xor_sync(~0u, c1, 4);
    float acc = b2 ? (c1 + s1) : (c0 + s0);
    acc += __shfl_xor_sync(~0u, acc, 8);
    acc += __shfl_xor_sync(~0u, acc, 16);
    return acc;
}

// ---------------------------------------------------------------------------
// Persistent compute (R10 shape: 4 CTAs/SM, 64 regs, warp-autonomous) plus
// zero-cost L2 prefetch of the NEXT group's W slice: by the time the next
// iteration's 8 W LDGs issue, their lines are L2-resident (~250 cyc instead
// of ~600 cyc DRAM), shrinking the serial W stall with no register/SMEM cost.
__global__ __launch_bounds__(256, 4) void compute_kernel(
    const float* __restrict__ x,      // [E, 128]
    const float* __restrict__ Wpool,  // [P, 64, 128]
    const float* __restrict__ bpool,  // [P, 64]
    float* __restrict__ out,          // [E, 64]
    int npool)
{
    int warp = threadIdx.x >> 5;
    int lane = threadIdx.x & 31;
    int stride = gridDim.x;

    int rloc = 4 * (lane & 1) + 2 * ((lane >> 1) & 1) + ((lane >> 2) & 1);
    int orow = 8 * warp + rloc;

    const float4* X  = reinterpret_cast<const float4*>(x);
    const float4* WP = reinterpret_cast<const float4*>(Wpool);
    float4 z = make_float4(0.f, 0.f, 0.f, 0.f);

    int w = blockIdx.x;
    int se_next = (w < npool) ? g_bucket[w * CAP + lane] : -1;

    while (w < npool) {
        int se = se_next;

        // W slice for this group: 8 x coalesced LDG.128 (512B each).
        const float4* Wg = WP + (size_t)w * 2048 + warp * 256;
        float4 wv[8];
        #pragma unroll
        for (int i = 0; i < 8; i++)
            wv[i] = Wg[i * 32 + lane];   // wv[i] = W[8*warp+i][4l..4l+4)

        // Prefetch NEXT group's edge ids (real load) and W slice (L2 prefetch).
        int wn = w + stride;
        se_next = -1;
        if (wn < npool) {
            se_next = g_bucket[wn * CAP + lane];
            const char* pf = reinterpret_cast<const char*>(WP + (size_t)wn * 2048 + warp * 256)
                             + lane * 16;
            #pragma unroll
            for (int i = 0; i < 8; i++)
                asm volatile("prefetch.global.L2 [%0];" :: "l"(pf + i * 512));
        }

        int c = __popc(__ballot_sync(~0u, se >= 0));     // group size 0..32
        if (c > 0) {
            float bias = bpool[(size_t)w * OUT_DIM + orow];

            // prime pair pipeline: edges 0,1
            int eA = __shfl_sync(~0u, se, 0);
            int eB = __shfl_sync(~0u, se, 1);
            float4 xA = X[(size_t)eA * 32 + lane];
            float4 xB = (c > 1) ? X[(size_t)eB * 32 + lane] : z;

            int t = 0;
            while (t + 2 <= c) {
                int eC = __shfl_sync(~0u, se, (t + 2) & 31);
                int eD = __shfl_sync(~0u, se, (t + 3) & 31);
                float4 xC = z, xD = z;
                if (t + 2 < c) xC = X[(size_t)eC * 32 + lane];
                if (t + 3 < c) xD = X[(size_t)eD * 32 + lane];

                float vA[8], vB[8];
                partials8(vA, wv, xA);
                partials8(vB, wv, xB);
                float accA = fold8(vA, lane);
                float accB = fold8(vB, lane);

                if (lane < 8) {
                    float yA = accA + bias;
                    float yB = accB + bias;
                    out[(size_t)eA * OUT_DIM + orow] = yA > 0.f ? yA : 0.f;
                    out[(size_t)eB * OUT_DIM + orow] = yB > 0.f ? yB : 0.f;
                }

                eA = eC; xA = xC;
                eB = eD; xB = xD;
                t += 2;
            }
            if (t < c) {                         // odd tail
                float vA[8];
                partials8(vA, wv, xA);
                float accA = fold8(vA, lane);
                if (lane < 8) {
                    float yA = accA + bias;
                    out[(size_t)eA * OUT_DIM + orow] = yA > 0.f ? yA : 0.f;
                }
            }
        }
        w = wn;
    }
}

// ---------------------------------------------------------------------------
// Spill slow path: normally zero work, early exit.
__global__ __launch_bounds__(256) void spill_kernel(
    const float* __restrict__ x,
    const float* __restrict__ Wpool,
    const float* __restrict__ bpool,
    const int*   __restrict__ idx,
    float* __restrict__ out,
    int npool)
{
    int nspill = g_counts[npool];
    if (nspill == 0) return;
    if (nspill > MAX_EDGES) nspill = MAX_EDGES;

    int warp = threadIdx.x >> 5;
    int lane = threadIdx.x & 31;
    const float4* X = reinterpret_cast<const float4*>(x);

    for (int s = blockIdx.x * 8 + warp; s < nspill; s += gridDim.x * 8) {
        int e = g_spill[s];
        int p = idx[e];
        const float4* Wr = reinterpret_cast<const float4*>(Wpool) + (size_t)p * 2048;
        #pragma unroll
        for (int rr = 0; rr < 2; rr++) {
            int row = lane * 2 + rr;
            float acc = 0.f;
            for (int kk = 0; kk < 32; kk++) {
                float4 a = Wr[row * 32 + kk];
                float4 b = X[(size_t)e * 32 + kk];
                acc = fmaf(a.x, b.x, acc);
                acc = fmaf(a.y, b.y, acc);
                acc = fmaf(a.z, b.z, acc);
                acc = fmaf(a.w, b.w, acc);
            }
            acc += bpool[(size_t)p * OUT_DIM + row];
            out[(size_t)e * OUT_DIM + row] = acc > 0.f ? acc : 0.f;
        }
    }
}

// ---------------------------------------------------------------------------
extern "C" void kernel_launch(void* const* d_in, const int* in_sizes, int n_in,
                              void* d_out, int out_size) {
    const float* x     = (const float*)d_in[0];  // [E,128,1]
    const int*   idx   = (const int*)d_in[1];    // [E]
    const float* Wpool = (const float*)d_in[2];  // [P,64,128]
    const float* bpool = (const float*)d_in[3];  // [P,64,1]
    float* out = (float*)d_out;                  // [E,64,1]

    int E     = in_sizes[1];
    int npool = in_sizes[3] / OUT_DIM;
    if (npool > MAX_POOL) npool = MAX_POOL;      // defensive

    void* counts_ptr = nullptr;
    void* bucket_ptr = nullptr;
    cudaGetSymbolAddress(&counts_ptr, g_counts);
    cudaGetSymbolAddress(&bucket_ptr, g_bucket);
    cudaMemsetAsync(counts_ptr, 0, (size_t)(npool + 1) * sizeof(int));
    cudaMemsetAsync(bucket_ptr, 0xFF, (size_t)npool * CAP * sizeof(int));

    int sms = 148;
    cudaDeviceGetAttribute(&sms, cudaDevAttrMultiProcessorCount, 0);

    int eb = (E + 255) / 256;
    bucket_kernel<<<eb, 256>>>(idx, E, npool);

    int cgrid = 4 * sms;
    if (cgrid > npool) cgrid = npool;
    compute_kernel<<<cgrid, 256>>>(x, Wpool, bpool, out, npool);
    spill_kernel<<<64, 256>>>(x, Wpool, bpool, idx, out, npool);
}

// round 15
// speedup vs baseline: 1.2213x; 1.0056x over previous
#include <cuda_runtime.h>
#include <cuda_bf16.h>
#include <cstdint>

#define OUT_DIM 64
#define IN_DIM 128
#define MAX_POOL 16384
#define MAX_EDGES 65536
#define CAP 32                 // bucket capacity per pool entry

__device__ int g_counts[MAX_POOL + 1];        // bucket alloc cursors + spill counter
__device__ int g_bucket[MAX_POOL * CAP];      // memset to -1 each call
__device__ int g_spill[MAX_EDGES];

// ---------------------------------------------------------------------------
// Single-pass counting scatter into fixed-capacity buckets; overflow -> spill.
__global__ void bucket_kernel(const int* __restrict__ idx, int E, int npool) {
    int i = blockIdx.x * blockDim.x + threadIdx.x;
    if (i < E) {
        int id = idx[i];
        int p = atomicAdd(&g_counts[id], 1);
        if (p < CAP) {
            g_bucket[id * CAP + p] = i;
        } else {
            int s = atomicAdd(&g_counts[npool], 1);
            if (s < MAX_EDGES) g_spill[s] = i;
        }
    }
}

// ---------------------------------------------------------------------------
__device__ __forceinline__ void cp_async16(unsigned int saddr, const void* gaddr) {
    asm volatile("cp.async.cg.shared.global [%0], [%1], 16;\n"
                 :: "r"(saddr), "l"(gaddr));
}
__device__ __forceinline__ void cp_async_commit() {
    asm volatile("cp.async.commit_group;\n" ::: "memory");
}
__device__ __forceinline__ void cp_async_wait0() {
    asm volatile("cp.async.wait_group 0;\n" ::: "memory");
}

__device__ __forceinline__ void partials8(float v[8], const float4 wv[8],
                                          const float4& xv) {
    #pragma unroll
    for (int i = 0; i < 8; i++) v[i] = wv[i].x * xv.x;
    #pragma unroll
    for (int i = 0; i < 8; i++) v[i] = fmaf(wv[i].y, xv.y, v[i]);
    #pragma unroll
    for (int i = 0; i < 8; i++) v[i] = fmaf(wv[i].z, xv.z, v[i]);
    #pragma unroll
    for (int i = 0; i < 8; i++) v[i] = fmaf(wv[i].w, xv.w, v[i]);
}

// 5-stage butterfly: 8 row-partials x 32 lanes -> final row value in lanes 0..7
__device__ __forceinline__ float fold8(const float v[8], int lane) {
    bool b0 = lane & 1;
    float a0, a1, a2, a3;
    {
        float p0 = __shfl_xor_sync(~0u, v[0], 1), p1 = __shfl_xor_sync(~0u, v[1], 1);
        float p2 = __shfl_xor_sync(~0u, v[2], 1), p3 = __shfl_xor_sync(~0u, v[3], 1);
        float p4 = __shfl_xor_sync(~0u, v[4], 1), p5 = __shfl_xor_sync(~0u, v[5], 1);
        float p6 = __shfl_xor_sync(~0u, v[6], 1), p7 = __shfl_xor_sync(~0u, v[7], 1);
        a0 = b0 ? (v[4] + p4) : (v[0] + p0);
        a1 = b0 ? (v[5] + p5) : (v[1] + p1);
        a2 = b0 ? (v[6] + p6) : (v[2] + p2);
        a3 = b0 ? (v[7] + p7) : (v[3] + p3);
    }
    bool b1 = lane & 2;
    float c0, c1;
    {
        float q0 = __shfl_xor_sync(~0u, a0, 2), q1 = __shfl_xor_sync(~0u, a1, 2);
        float q2 = __shfl_xor_sync(~0u, a2, 2), q3 = __shfl_xor_sync(~0u, a3, 2);
        c0 = b1 ? (a2 + q2) : (a0 + q0);
        c1 = b1 ? (a3 + q3) : (a1 + q1);
    }
    bool b2 = lane & 4;
    float s0 = __shfl_xor_sync(~0u, c0, 4), s1 = __shfl_xor_sync(~0u, c1, 4);
    float acc = b2 ? (c1 + s1) : (c0 + s0);
    acc += __shfl_xor_sync(~0u, acc, 8);
    acc += __shfl_xor_sync(~0u, acc, 16);
    return acc;
}

// ---------------------------------------------------------------------------
// Persistent compute with PER-WARP cp.async W prefetch (no barriers, no extra
// registers). Each warp owns a private 4KB SMEM buffer; at each group it
// waits for last iteration's prefetch, LDS's W to registers (29cyc), then
// immediately streams the NEXT group's W slice into the same buffer while
// computing the current group. W DRAM fetch fully overlaps compute.
__global__ __launch_bounds__(256, 4) void compute_kernel(
    const float* __restrict__ x,      // [E, 128]
    const float* __restrict__ Wpool,  // [P, 64, 128]
    const float* __restrict__ bpool,  // [P, 64]
    float* __restrict__ out,          // [E, 64]
    int npool)
{
    __shared__ float4 sW[8][256];     // 8 warps x 4KB private buffers

    int warp = threadIdx.x >> 5;
    int lane = threadIdx.x & 31;
    int stride = gridDim.x;

    int rloc = 4 * (lane & 1) + 2 * ((lane >> 1) & 1) + ((lane >> 2) & 1);
    int orow = 8 * warp + rloc;

    const float4* X  = reinterpret_cast<const float4*>(x);
    const float4* WP = reinterpret_cast<const float4*>(Wpool);
    float4 z = make_float4(0.f, 0.f, 0.f, 0.f);

    unsigned int sbuf = (unsigned int)__cvta_generic_to_shared(&sW[warp][0]);

    int w = blockIdx.x;
    int se_next = -1;

    // prologue: stage first group's W into own buffer + its edge ids
    if (w < npool) {
        se_next = g_bucket[w * CAP + lane];
        const float4* src = WP + (size_t)w * 2048 + warp * 256;
        #pragma unroll
        for (int i = 0; i < 8; i++)
            cp_async16(sbuf + (i * 32 + lane) * 16, src + i * 32 + lane);
    }
    cp_async_commit();

    while (w < npool) {
        int se = se_next;
        int c = __popc(__ballot_sync(~0u, se >= 0));     // group size 0..32

        // issue this group's first pair x loads (independent of W)
        int eA = __shfl_sync(~0u, se, 0);
        int eB = __shfl_sync(~0u, se, 1);
        float4 xA = z, xB = z;
        if (c > 0) xA = X[(size_t)eA * 32 + lane];
        if (c > 1) xB = X[(size_t)eB * 32 + lane];

        // W ready in own buffer (prefetched last iteration) -> registers
        cp_async_wait0();
        float4 wv[8];
        #pragma unroll
        for (int i = 0; i < 8; i++)
            wv[i] = sW[warp][i * 32 + lane];             // wv[i] = W[8w+i][4l..4l+4)

        // immediately stream NEXT group's W into the same private buffer
        int wn = w + stride;
        se_next = -1;
        if (wn < npool) {
            se_next = g_bucket[wn * CAP + lane];
            const float4* src = WP + (size_t)wn * 2048 + warp * 256;
            #pragma unroll
            for (int i = 0; i < 8; i++)
                cp_async16(sbuf + (i * 32 + lane) * 16, src + i * 32 + lane);
        }
        cp_async_commit();

        if (c > 0) {
            float bias = bpool[(size_t)w * OUT_DIM + orow];

            int t = 0;
            while (t + 2 <= c) {
                int eC = __shfl_sync(~0u, se, (t + 2) & 31);
                int eD = __shfl_sync(~0u, se, (t + 3) & 31);
                float4 xC = z, xD = z;
                if (t + 2 < c) xC = X[(size_t)eC * 32 + lane];
                if (t + 3 < c) xD = X[(size_t)eD * 32 + lane];

                float vA[8], vB[8];
                partials8(vA, wv, xA);
                partials8(vB, wv, xB);
                float accA = fold8(vA, lane);
                float accB = fold8(vB, lane);

                if (lane < 8) {
                    float yA = accA + bias;
                    float yB = accB + bias;
                    out[(size_t)eA * OUT_DIM + orow] = yA > 0.f ? yA : 0.f;
                    out[(size_t)eB * OUT_DIM + orow] = yB > 0.f ? yB : 0.f;
                }

                eA = eC; xA = xC;
                eB = eD; xB = xD;
                t += 2;
            }
            if (t < c) {                         // odd tail
                float vA[8];
                partials8(vA, wv, xA);
                float accA = fold8(vA, lane);
                if (lane < 8) {
                    float yA = accA + bias;
                    out[(size_t)eA * OUT_DIM + orow] = yA > 0.f ? yA : 0.f;
                }
            }
        }
        w = wn;
    }
}

// ---------------------------------------------------------------------------
// Spill slow path: normally zero work, early exit.
__global__ __launch_bounds__(256) void spill_kernel(
    const float* __restrict__ x,
    const float* __restrict__ Wpool,
    const float* __restrict__ bpool,
    const int*   __restrict__ idx,
    float* __restrict__ out,
    int npool)
{
    int nspill = g_counts[npool];
    if (nspill == 0) return;
    if (nspill > MAX_EDGES) nspill = MAX_EDGES;

    int warp = threadIdx.x >> 5;
    int lane = threadIdx.x & 31;
    const float4* X = reinterpret_cast<const float4*>(x);

    for (int s = blockIdx.x * 8 + warp; s < nspill; s += gridDim.x * 8) {
        int e = g_spill[s];
        int p = idx[e];
        const float4* Wr = reinterpret_cast<const float4*>(Wpool) + (size_t)p * 2048;
        #pragma unroll
        for (int rr = 0; rr < 2; rr++) {
            int row = lane * 2 + rr;
            float acc = 0.f;
            for (int kk = 0; kk < 32; kk++) {
                float4 a = Wr[row * 32 + kk];
                float4 b = X[(size_t)e * 32 + kk];
                acc = fmaf(a.x, b.x, acc);
                acc = fmaf(a.y, b.y, acc);
                acc = fmaf(a.z, b.z, acc);
                acc = fmaf(a.w, b.w, acc);
            }
            acc += bpool[(size_t)p * OUT_DIM + row];
            out[(size_t)e * OUT_DIM + row] = acc > 0.f ? acc : 0.f;
        }
    }
}

// ---------------------------------------------------------------------------
extern "C" void kernel_launch(void* const* d_in, const int* in_sizes, int n_in,
                              void* d_out, int out_size) {
    const float* x     = (const float*)d_in[0];  // [E,128,1]
    const int*   idx   = (const int*)d_in[1];    // [E]
    const float* Wpool = (const float*)d_in[2];  // [P,64,128]
    const float* bpool = (const float*)d_in[3];  // [P,64,1]
    float* out = (float*)d_out;                  // [E,64,1]

    int E     = in_sizes[1];
    int npool = in_sizes[3] / OUT_DIM;
    if (npool > MAX_POOL) npool = MAX_POOL;      // defensive

    void* counts_ptr = nullptr;
    void* bucket_ptr = nullptr;
    cudaGetSymbolAddress(&counts_ptr, g_counts);
    cudaGetSymbolAddress(&bucket_ptr, g_bucket);
    cudaMemsetAsync(counts_ptr, 0, (size_t)(npool + 1) * sizeof(int));
    cudaMemsetAsync(bucket_ptr, 0xFF, (size_t)npool * CAP * sizeof(int));

    int sms = 148;
    cudaDeviceGetAttribute(&sms, cudaDevAttrMultiProcessorCount, 0);

    int eb = (E + 255) / 256;
    bucket_kernel<<<eb, 256>>>(idx, E, npool);

    int cgrid = 4 * sms;
    if (cgrid > npool) cgrid = npool;
    compute_kernel<<<cgrid, 256>>>(x, Wpool, bpool, out, npool);
    spill_kernel<<<64, 256>>>(x, Wpool, bpool, idx, out, npool);
}

// round 16
// speedup vs baseline: 1.3042x; 1.0679x over previous
#include <cuda_runtime.h>
#include <cuda_bf16.h>
#include <cstdint>

#define OUT_DIM 64
#define IN_DIM 128
#define MAX_POOL 16384
#define MAX_EDGES 65536
#define CAP 32                 // bucket capacity per pool entry

__device__ int g_counts[MAX_POOL + 1];        // bucket alloc cursors + spill counter
__device__ int g_bucket[MAX_POOL * CAP];      // memset to -1 each call
__device__ int g_spill[MAX_EDGES];
__device__ int g_work;                        // work-steal cursor (chunks of 2 groups)

// ---------------------------------------------------------------------------
// Single-pass counting scatter into fixed-capacity buckets; overflow -> spill.
// Also initializes the work-steal cursor past the deterministic first chunks.
__global__ void bucket_kernel(const int* __restrict__ idx, int E, int npool,
                              int work_init) {
    int i = blockIdx.x * blockDim.x + threadIdx.x;
    if (i == 0) g_work = work_init;
    if (i < E) {
        int id = idx[i];
        int p = atomicAdd(&g_counts[id], 1);
        if (p < CAP) {
            g_bucket[id * CAP + p] = i;
        } else {
            int s = atomicAdd(&g_counts[npool], 1);
            if (s < MAX_EDGES) g_spill[s] = i;
        }
    }
}

// ---------------------------------------------------------------------------
__device__ __forceinline__ void partials8(float v[8], const float4 wv[8],
                                          const float4& xv) {
    #pragma unroll
    for (int i = 0; i < 8; i++) v[i] = wv[i].x * xv.x;
    #pragma unroll
    for (int i = 0; i < 8; i++) v[i] = fmaf(wv[i].y, xv.y, v[i]);
    #pragma unroll
    for (int i = 0; i < 8; i++) v[i] = fmaf(wv[i].z, xv.z, v[i]);
    #pragma unroll
    for (int i = 0; i < 8; i++) v[i] = fmaf(wv[i].w, xv.w, v[i]);
}

// Swap-select butterfly: 8 row-partials x 32 lanes -> final row value in
// lanes 0..7 (row rloc = 4*b0 + 2*b1 + b2). 9 SHFL instead of 16.
__device__ __forceinline__ float fold8(const float v[8], int lane) {
    bool b0 = lane & 1;
    float t0 = b0 ? v[4] : v[0], u0 = b0 ? v[0] : v[4];
    float t1 = b0 ? v[5] : v[1], u1 = b0 ? v[1] : v[5];
    float t2 = b0 ? v[6] : v[2], u2 = b0 ? v[2] : v[6];
    float t3 = b0 ? v[7] : v[3], u3 = b0 ? v[3] : v[7];
    float a0 = t0 + __shfl_xor_sync(~0u, u0, 1);
    float a1 = t1 + __shfl_xor_sync(~0u, u1, 1);
    float a2 = t2 + __shfl_xor_sync(~0u, u2, 1);
    float a3 = t3 + __shfl_xor_sync(~0u, u3, 1);

    bool b1 = lane & 2;
    float s0 = b1 ? a2 : a0, w0 = b1 ? a0 : a2;
    float s1 = b1 ? a3 : a1, w1 = b1 ? a1 : a3;
    float c0 = s0 + __shfl_xor_sync(~0u, w0, 2);
    float c1 = s1 + __shfl_xor_sync(~0u, w1, 2);

    bool b2 = lane & 4;
    float d0 = b2 ? c1 : c0, d1 = b2 ? c0 : c1;
    float acc = d0 + __shfl_xor_sync(~0u, d1, 4);
    acc += __shfl_xor_sync(~0u, acc, 8);
    acc += __shfl_xor_sync(~0u, acc, 16);
    return acc;
}

// ---------------------------------------------------------------------------
// One group's work for this CTA (R10-proven shape, warp-autonomous).
__device__ __forceinline__ void process_group(
    int w, int se, int warp, int lane, int orow,
    const float4* __restrict__ X,
    const float4* __restrict__ WP,
    const float* __restrict__ bpool,
    float* __restrict__ out)
{
    // W slice: 8 x coalesced LDG.128 (512B each warp instruction).
    const float4* Wg = WP + (size_t)w * 2048 + warp * 256;
    float4 wv[8];
    #pragma unroll
    for (int i = 0; i < 8; i++)
        wv[i] = Wg[i * 32 + lane];   // wv[i] = W[8*warp+i][4l..4l+4)

    int c = __popc(__ballot_sync(~0u, se >= 0));     // group size 0..32
    if (c == 0) return;

    float bias = bpool[(size_t)w * OUT_DIM + orow];
    float4 z = make_float4(0.f, 0.f, 0.f, 0.f);

    // prime pair pipeline: edges 0,1
    int eA = __shfl_sync(~0u, se, 0);
    int eB = __shfl_sync(~0u, se, 1);
    float4 xA = X[(size_t)eA * 32 + lane];
    float4 xB = (c > 1) ? X[(size_t)eB * 32 + lane] : z;

    int t = 0;
    while (t + 2 <= c) {
        int eC = __shfl_sync(~0u, se, (t + 2) & 31);
        int eD = __shfl_sync(~0u, se, (t + 3) & 31);
        float4 xC = z, xD = z;
        if (t + 2 < c) xC = X[(size_t)eC * 32 + lane];
        if (t + 3 < c) xD = X[(size_t)eD * 32 + lane];

        float vA[8], vB[8];
        partials8(vA, wv, xA);
        partials8(vB, wv, xB);
        float accA = fold8(vA, lane);
        float accB = fold8(vB, lane);

        if (lane < 8) {
            float yA = accA + bias;
            float yB = accB + bias;
            out[(size_t)eA * OUT_DIM + orow] = yA > 0.f ? yA : 0.f;
            out[(size_t)eB * OUT_DIM + orow] = yB > 0.f ? yB : 0.f;
        }

        eA = eC; xA = xC;
        eB = eD; xB = xD;
        t += 2;
    }
    if (t < c) {                         // odd tail
        float vA[8];
        partials8(vA, wv, xA);
        float accA = fold8(vA, lane);
        if (lane < 8) {
            float yA = accA + bias;
            out[(size_t)eA * OUT_DIM + orow] = yA > 0.f ? yA : 0.f;
        }
    }
}

// ---------------------------------------------------------------------------
// Persistent compute with chunk-2 work stealing: first chunk deterministic,
// then one atomicAdd per chunk (issued a full group ahead) published to the
// CTA via one __syncthreads mid-chunk. Near-perfect load balance.
__global__ __launch_bounds__(256, 4) void compute_kernel(
    const float* __restrict__ x,      // [E, 128]
    const float* __restrict__ Wpool,  // [P, 64, 128]
    const float* __restrict__ bpool,  // [P, 64]
    float* __restrict__ out,          // [E, 64]
    int npool)
{
    __shared__ int s_next;

    int warp = threadIdx.x >> 5;
    int lane = threadIdx.x & 31;

    int rloc = 4 * (lane & 1) + 2 * ((lane >> 1) & 1) + ((lane >> 2) & 1);
    int orow = 8 * warp + rloc;

    const float4* X  = reinterpret_cast<const float4*>(x);
    const float4* WP = reinterpret_cast<const float4*>(Wpool);

    int w = blockIdx.x * 2;                          // deterministic first chunk
    if (w >= npool) return;
    int se = g_bucket[w * CAP + lane];               // pos-0 ids

    for (;;) {
        // ---- pos 0: group w ----
        if (threadIdx.x == 0) s_next = atomicAdd(&g_work, 2);
        int w1 = w + 1;
        int se1 = (w1 < npool) ? g_bucket[w1 * CAP + lane] : -1;  // prefetch pos-1 ids
        if (w < npool) process_group(w, se, warp, lane, orow, X, WP, bpool, out);

        __syncthreads();                             // steal result visible
        int wn = s_next;

        // ---- pos 1: group w1 ----
        int se_n = (wn < npool) ? g_bucket[wn * CAP + lane] : -1; // prefetch stolen ids
        if (w1 < npool) process_group(w1, se1, warp, lane, orow, X, WP, bpool, out);

        if (wn >= npool) break;
        w = wn; se = se_n;
    }
}

// ---------------------------------------------------------------------------
// Spill slow path: normally zero work, early exit.
__global__ __launch_bounds__(256) void spill_kernel(
    const float* __restrict__ x,
    const float* __restrict__ Wpool,
    const float* __restrict__ bpool,
    const int*   __restrict__ idx,
    float* __restrict__ out,
    int npool)
{
    int nspill = g_counts[npool];
    if (nspill == 0) return;
    if (nspill > MAX_EDGES) nspill = MAX_EDGES;

    int warp = threadIdx.x >> 5;
    int lane = threadIdx.x & 31;
    const float4* X = reinterpret_cast<const float4*>(x);

    for (int s = blockIdx.x * 8 + warp; s < nspill; s += gridDim.x * 8) {
        int e = g_spill[s];
        int p = idx[e];
        const float4* Wr = reinterpret_cast<const float4*>(Wpool) + (size_t)p * 2048;
        #pragma unroll
        for (int rr = 0; rr < 2; rr++) {
            int row = lane * 2 + rr;
            float acc = 0.f;
            for (int kk = 0; kk < 32; kk++) {
                float4 a = Wr[row * 32 + kk];
                float4 b = X[(size_t)e * 32 + kk];
                acc = fmaf(a.x, b.x, acc);
                acc = fmaf(a.y, b.y, acc);
                acc = fmaf(a.z, b.z, acc);
                acc = fmaf(a.w, b.w, acc);
            }
            acc += bpool[(size_t)p * OUT_DIM + row];
            out[(size_t)e * OUT_DIM + row] = acc > 0.f ? acc : 0.f;
        }
    }
}

// ---------------------------------------------------------------------------
extern "C" void kernel_launch(void* const* d_in, const int* in_sizes, int n_in,
                              void* d_out, int out_size) {
    const float* x     = (const float*)d_in[0];  // [E,128,1]
    const int*   idx   = (const int*)d_in[1];    // [E]
    const float* Wpool = (const float*)d_in[2];  // [P,64,128]
    const float* bpool = (const float*)d_in[3];  // [P,64,1]
    float* out = (float*)d_out;                  // [E,64,1]

    int E     = in_sizes[1];
    int npool = in_sizes[3] / OUT_DIM;
    if (npool > MAX_POOL) npool = MAX_POOL;      // defensive

    void* counts_ptr = nullptr;
    void* bucket_ptr = nullptr;
    cudaGetSymbolAddress(&counts_ptr, g_counts);
    cudaGetSymbolAddress(&bucket_ptr, g_bucket);
    cudaMemsetAsync(counts_ptr, 0, (size_t)(npool + 1) * sizeof(int));
    cudaMemsetAsync(bucket_ptr, 0xFF, (size_t)npool * CAP * sizeof(int));

    int sms = 148;
    cudaDeviceGetAttribute(&sms, cudaDevAttrMultiProcessorCount, 0);
    int cgrid = 4 * sms;
    int nchunks = (npool + 1) / 2;
    if (cgrid > nchunks) cgrid = nchunks;
    if (cgrid < 1) cgrid = 1;

    int eb = (E + 255) / 256;
    bucket_kernel<<<eb, 256>>>(idx, E, npool, 2 * cgrid);
    compute_kernel<<<cgrid, 256>>>(x, Wpool, bpool, out, npool);
    spill_kernel<<<64, 256>>>(x, Wpool, bpool, idx, out, npool);
}

// round 17
// speedup vs baseline: 1.3404x; 1.0278x over previous
#include <cuda_runtime.h>
#include <cuda_bf16.h>
#include <cstdint>

#define OUT_DIM 64
#define IN_DIM 128
#define MAX_POOL 16384
#define MAX_EDGES 65536
#define CAP 32                 // bucket capacity per pool entry

__device__ int g_counts[MAX_POOL + 1];        // bucket alloc cursors + spill counter
__device__ int g_bucket[MAX_POOL * CAP];
__device__ int g_spill[MAX_EDGES];
__device__ int g_work;                        // work-steal cursor (chunks of 2 groups)

// ---------------------------------------------------------------------------
// Single-pass counting scatter into fixed-capacity buckets; overflow -> spill.
__global__ void bucket_kernel(const int* __restrict__ idx, int E, int npool,
                              int work_init) {
    int i = blockIdx.x * blockDim.x + threadIdx.x;
    if (i == 0) g_work = work_init;
    if (i < E) {
        int id = idx[i];
        int p = atomicAdd(&g_counts[id], 1);
        if (p < CAP) {
            g_bucket[id * CAP + p] = i;
        } else {
            int s = atomicAdd(&g_counts[npool], 1);
            if (s < MAX_EDGES) g_spill[s] = i;
        }
    }
}

// ---------------------------------------------------------------------------
__device__ __forceinline__ void partials8(float v[8], const float4 wv[8],
                                          const float4& xv) {
    #pragma unroll
    for (int i = 0; i < 8; i++) v[i] = wv[i].x * xv.x;
    #pragma unroll
    for (int i = 0; i < 8; i++) v[i] = fmaf(wv[i].y, xv.y, v[i]);
    #pragma unroll
    for (int i = 0; i < 8; i++) v[i] = fmaf(wv[i].z, xv.z, v[i]);
    #pragma unroll
    for (int i = 0; i < 8; i++) v[i] = fmaf(wv[i].w, xv.w, v[i]);
}

// Swap-select butterfly: 8 row-partials x 32 lanes -> final row value in
// lanes 0..7 (row rloc = 4*b0 + 2*b1 + b2). 9 SHFL total.
__device__ __forceinline__ float fold8(const float v[8], int lane) {
    bool b0 = lane & 1;
    float t0 = b0 ? v[4] : v[0], u0 = b0 ? v[0] : v[4];
    float t1 = b0 ? v[5] : v[1], u1 = b0 ? v[1] : v[5];
    float t2 = b0 ? v[6] : v[2], u2 = b0 ? v[2] : v[6];
    float t3 = b0 ? v[7] : v[3], u3 = b0 ? v[3] : v[7];
    float a0 = t0 + __shfl_xor_sync(~0u, u0, 1);
    float a1 = t1 + __shfl_xor_sync(~0u, u1, 1);
    float a2 = t2 + __shfl_xor_sync(~0u, u2, 1);
    float a3 = t3 + __shfl_xor_sync(~0u, u3, 1);

    bool b1 = lane & 2;
    float s0 = b1 ? a2 : a0, w0 = b1 ? a0 : a2;
    float s1 = b1 ? a3 : a1, w1 = b1 ? a1 : a3;
    float c0 = s0 + __shfl_xor_sync(~0u, w0, 2);
    float c1 = s1 + __shfl_xor_sync(~0u, w1, 2);

    bool b2 = lane & 4;
    float d0 = b2 ? c1 : c0, d1 = b2 ? c0 : c1;
    float acc = d0 + __shfl_xor_sync(~0u, d1, 4);
    acc += __shfl_xor_sync(~0u, acc, 8);
    acc += __shfl_xor_sync(~0u, acc, 16);
    return acc;
}

// ---------------------------------------------------------------------------
// One group's work (proven shape): W straight to registers, pair-pipelined x.
__device__ __forceinline__ void process_group(
    int w, int se, int c, int warp, int lane, int orow,
    const float4* __restrict__ X,
    const float4* __restrict__ WP,
    const float* __restrict__ bpool,
    float* __restrict__ out)
{
    // W slice: 8 x coalesced LDG.128 (512B each warp instruction).
    const float4* Wg = WP + (size_t)w * 2048 + warp * 256;
    float4 wv[8];
    #pragma unroll
    for (int i = 0; i < 8; i++)
        wv[i] = Wg[i * 32 + lane];   // wv[i] = W[8*warp+i][4l..4l+4)

    if (c == 0) return;

    float bias = bpool[(size_t)w * OUT_DIM + orow];
    float4 z = make_float4(0.f, 0.f, 0.f, 0.f);

    int eA = __shfl_sync(~0u, se, 0);
    int eB = __shfl_sync(~0u, se, 1);
    float4 xA = X[(size_t)eA * 32 + lane];
    float4 xB = (c > 1) ? X[(size_t)eB * 32 + lane] : z;

    int t = 0;
    while (t + 2 <= c) {
        int eC = __shfl_sync(~0u, se, (t + 2) & 31);
        int eD = __shfl_sync(~0u, se, (t + 3) & 31);
        float4 xC = z, xD = z;
        if (t + 2 < c) xC = X[(size_t)eC * 32 + lane];
        if (t + 3 < c) xD = X[(size_t)eD * 32 + lane];

        float vA[8], vB[8];
        partials8(vA, wv, xA);
        partials8(vB, wv, xB);
        float accA = fold8(vA, lane);
        float accB = fold8(vB, lane);

        if (lane < 8) {
            float yA = accA + bias;
            float yB = accB + bias;
            out[(size_t)eA * OUT_DIM + orow] = yA > 0.f ? yA : 0.f;
            out[(size_t)eB * OUT_DIM + orow] = yB > 0.f ? yB : 0.f;
        }

        eA = eC; xA = xC;
        eB = eD; xB = xD;
        t += 2;
    }
    if (t < c) {
        float vA[8];
        partials8(vA, wv, xA);
        float accA = fold8(vA, lane);
        if (lane < 8) {
            float yA = accA + bias;
            out[(size_t)eA * OUT_DIM + orow] = yA > 0.f ? yA : 0.f;
        }
    }
}

// ---------------------------------------------------------------------------
// Persistent compute with BARRIER-FREE work distribution: warp0/lane0 steals
// chunk i+1 at the top of chunk i and publishes it in a volatile smem ring;
// every warp walks the identical chunk sequence at its own pace (spin only if
// it outruns warp0). Warps never phase-align, so per-warp W bursts stay
// decorrelated and DRAM demand stays continuous.
__global__ __launch_bounds__(256, 4) void compute_kernel(
    const float* __restrict__ x,      // [E, 128]
    const float* __restrict__ Wpool,  // [P, 64, 128]
    const float* __restrict__ bpool,  // [P, 64]
    float* __restrict__ out,          // [E, 64]
    int npool)
{
    __shared__ int s_ring[64];
    __shared__ int s_wr;

    int tid  = threadIdx.x;
    int warp = tid >> 5;
    int lane = tid & 31;

    if (tid == 0) *(volatile int*)&s_wr = 1;   // entries < 1 never read
    __syncthreads();                            // once, at kernel start

    volatile int* vwr   = &s_wr;
    volatile int* vring = s_ring;

    int rloc = 4 * (lane & 1) + 2 * ((lane >> 1) & 1) + ((lane >> 2) & 1);
    int orow = 8 * warp + rloc;

    const float4* X  = reinterpret_cast<const float4*>(x);
    const float4* WP = reinterpret_cast<const float4*>(Wpool);

    int i  = 0;
    int wb = blockIdx.x * 2;                    // deterministic first chunk
    bool have = false;
    int ps0 = 0, ps1 = 0;                       // prefetched edge-id slices

    while (wb < npool) {
        // warp0/lane0: steal chunk i+1 and publish
        if (tid == 0) {
            int v = atomicAdd(&g_work, 2);
            vring[(i + 1) & 63] = v;
            __threadfence_block();
            *vwr = i + 2;
        }

        int w1 = wb + 1;
        int c0 = min(g_counts[wb], CAP);
        int c1 = (w1 < npool) ? min(g_counts[w1], CAP) : 0;
        int se0, se1;
        if (have) { se0 = ps0; se1 = ps1; }
        else {
            se0 = g_bucket[wb * CAP + lane];
            se1 = (w1 < npool) ? g_bucket[w1 * CAP + lane] : 0;
        }

        process_group(wb, se0, c0, warp, lane, orow, X, WP, bpool, out);

        // peek chunk i+1 (posted at top of this chunk by warp0) + prefetch ids
        int j = i + 1;
        int wbn = npool;
        bool hn = false;
        if (*vwr > j) {
            wbn = vring[j & 63];
            hn = true;
            if (wbn < npool) {
                ps0 = g_bucket[wbn * CAP + lane];
                ps1 = (wbn + 1 < npool) ? g_bucket[(wbn + 1) * CAP + lane] : 0;
            }
        }

        if (w1 < npool)
            process_group(w1, se1, c1, warp, lane, orow, X, WP, bpool, out);

        if (!hn) {                              // outran warp0: rare spin
            while (*vwr <= j) __nanosleep(64);
            wbn = vring[j & 63];
            have = false;
        } else {
            have = true;
        }
        wb = wbn;
        i  = j;
    }
}

// ---------------------------------------------------------------------------
// Spill slow path: normally zero work, early exit.
__global__ __launch_bounds__(256) void spill_kernel(
    const float* __restrict__ x,
    const float* __restrict__ Wpool,
    const float* __restrict__ bpool,
    const int*   __restrict__ idx,
    float* __restrict__ out,
    int npool)
{
    int nspill = g_counts[npool];
    if (nspill == 0) return;
    if (nspill > MAX_EDGES) nspill = MAX_EDGES;

    int warp = threadIdx.x >> 5;
    int lane = threadIdx.x & 31;
    const float4* X = reinterpret_cast<const float4*>(x);

    for (int s = blockIdx.x * 8 + warp; s < nspill; s += gridDim.x * 8) {
        int e = g_spill[s];
        int p = idx[e];
        const float4* Wr = reinterpret_cast<const float4*>(Wpool) + (size_t)p * 2048;
        #pragma unroll
        for (int rr = 0; rr < 2; rr++) {
            int row = lane * 2 + rr;
            float acc = 0.f;
            for (int kk = 0; kk < 32; kk++) {
                float4 a = Wr[row * 32 + kk];
                float4 b = X[(size_t)e * 32 + kk];
                acc = fmaf(a.x, b.x, acc);
                acc = fmaf(a.y, b.y, acc);
                acc = fmaf(a.z, b.z, acc);
                acc = fmaf(a.w, b.w, acc);
            }
            acc += bpool[(size_t)p * OUT_DIM + row];
            out[(size_t)e * OUT_DIM + row] = acc > 0.f ? acc : 0.f;
        }
    }
}

// ---------------------------------------------------------------------------
extern "C" void kernel_launch(void* const* d_in, const int* in_sizes, int n_in,
                              void* d_out, int out_size) {
    const float* x     = (const float*)d_in[0];  // [E,128,1]
    const int*   idx   = (const int*)d_in[1];    // [E]
    const float* Wpool = (const float*)d_in[2];  // [P,64,128]
    const float* bpool = (const float*)d_in[3];  // [P,64,1]
    float* out = (float*)d_out;                  // [E,64,1]

    int E     = in_sizes[1];
    int npool = in_sizes[3] / OUT_DIM;
    if (npool > MAX_POOL) npool = MAX_POOL;      // defensive

    void* counts_ptr = nullptr;
    cudaGetSymbolAddress(&counts_ptr, g_counts);
    cudaMemsetAsync(counts_ptr, 0, (size_t)(npool + 1) * sizeof(int));

    int sms = 148;
    cudaDeviceGetAttribute(&sms, cudaDevAttrMultiProcessorCount, 0);
    int cgrid = 4 * sms;
    int nchunks = (npool + 1) / 2;
    if (cgrid > nchunks) cgrid = nchunks;
    if (cgrid < 1) cgrid = 1;

    int eb = (E + 255) / 256;
    bucket_kernel<<<eb, 256>>>(idx, E, npool, 2 * cgrid);
    compute_kernel<<<cgrid, 256>>>(x, Wpool, bpool, out, npool);
    spill_kernel<<<64, 256>>>(x, Wpool, bpool, idx, out, npool);
}